// round 7
// baseline (speedup 1.0000x reference)
#include <cuda_runtime.h>
#include <cuda_fp16.h>
#include <math.h>
#include <stdint.h>

#define T_STEPS 256
#define B_SZ    256
#define I_SZ    128
#define N_SZ    1024
#define O_SZ    64
#define M_ROWS  512

#define GRID_MAIN 128
#define BK 64              // k per chunk (halves)
#define NCHUNK (N_SZ / BK) // 16
#define LSTR 33

#define WSTR_H 1032        // W smem row stride (halves)
#define ASTR_H 72          // A smem row stride (halves)
#define ABUF_B 18432       // one A buffer: 128 * 72 * 2

// ---- shared memory byte offsets ----
#define OFF_W     0                        // 32*1032*2 = 66048
#define OFF_A     66048                    // 3 x 18432 = 55296
#define OFF_SLOC  121344                   // 128*33 floats
#define OFF_XS    138240
#define OFF_KS    155136
#define OFF_FCS   172032
#define OFF_BHS   172160
#define SMEM_BYTES 172288

__device__ __half g_Sb[4][M_ROWS * N_SZ];  // rotating state buffers (fp16)
__device__ float  g_X [M_ROWS * N_SZ];
__device__ float  g_F0[B_SZ * N_SZ];
__device__ float  g_fc[N_SZ];
__device__ unsigned g_done[128 * 32];      // per-CTA stage counter, 128B padded

__constant__ float C_H     = 0.05f;
__constant__ float C_OMEGA = 6.283185307179586f;
__constant__ float C_GAMMA = 0.1f;
__constant__ float C_LAM   = 1.0f;
__constant__ float C_GAIN  = 0.03125f;

// ---------------------------------------------------------------------------
__global__ void init_kernel(const float* __restrict__ b_ih) {
    int idx = blockIdx.x * blockDim.x + threadIdx.x;
    int stride = gridDim.x * blockDim.x;
    for (int i = idx; i < M_ROWS * N_SZ; i += stride) g_Sb[3][i] = __float2half(0.0f);
    for (int i = idx; i < 128 * 32; i += stride) g_done[i] = 0u;
    if (idx < N_SZ) g_fc[idx] = tanhf(b_ih[idx]);
}

__global__ void forcing_kernel(const float* __restrict__ batch,
                               const float* __restrict__ W_ih,
                               const float* __restrict__ b_ih) {
    int idx = blockIdx.x * blockDim.x + threadIdx.x;
    int b = idx >> 10;
    int n = idx & (N_SZ - 1);
    const float4* xp = (const float4*)(batch + b * I_SZ);
    const float4* wp = (const float4*)(W_ih + n * I_SZ);
    float s = 0.0f;
#pragma unroll 8
    for (int i = 0; i < I_SZ / 4; ++i) {
        float4 x = __ldg(xp + i);
        float4 w = __ldg(wp + i);
        s += x.x * w.x + x.y * w.y + x.z * w.z + x.w * w.w;
    }
    g_F0[idx] = tanhf(s + __ldg(b_ih + n));
}

// ---------------------------------------------------------------------------
__device__ __forceinline__ void wait_flag(const unsigned* p, unsigned need) {
    unsigned v;
    do {
        asm volatile("ld.acquire.gpu.u32 %0, [%1];" : "=r"(v) : "l"(p) : "memory");
    } while (v < need);
}

// ---------------------------------------------------------------------------
__device__ __forceinline__ void mma_f16(float* d, uint32_t a0, uint32_t a1,
                                        uint32_t a2, uint32_t a3,
                                        uint32_t b0, uint32_t b1) {
    asm volatile(
        "mma.sync.aligned.m16n8k16.row.col.f32.f16.f16.f32 "
        "{%0,%1,%2,%3},{%4,%5,%6,%7},{%8,%9},{%0,%1,%2,%3};"
        : "+f"(d[0]), "+f"(d[1]), "+f"(d[2]), "+f"(d[3])
        : "r"(a0), "r"(a1), "r"(a2), "r"(a3), "r"(b0), "r"(b1));
}

__device__ __forceinline__ void ldsm4(uint32_t& r0, uint32_t& r1, uint32_t& r2,
                                      uint32_t& r3, uint32_t addr) {
    asm volatile("ldmatrix.sync.aligned.m8n8.x4.shared.b16 {%0,%1,%2,%3}, [%4];"
                 : "=r"(r0), "=r"(r1), "=r"(r2), "=r"(r3) : "r"(addr));
}

__device__ __forceinline__ void cp16(uint32_t s, const void* g) {
    asm volatile("cp.async.cg.shared.global [%0], [%1], 16;"
                 :: "r"(s), "l"(g) : "memory");
}
__device__ __forceinline__ void cp_commit() {
    asm volatile("cp.async.commit_group;" ::: "memory");
}

__device__ __forceinline__ uint32_t smem_u32(const void* p) {
    uint32_t a;
    asm("{ .reg .u64 t; cvta.to.shared.u64 t, %1; cvt.u32.u64 %0, t; }" : "=r"(a) : "l"(p));
    return a;
}

// ---------------------------------------------------------------------------
// main persistent kernel — barrier-free producer/consumer pipeline.
// Grid 128 = 4 independent 32-CTA groups. Output of stage sig -> g_Sb[sig&3].
// Chunk c of a stage's input is produced by group CTAs bn=2c,2c+1 only.
// ---------------------------------------------------------------------------
__global__ void __launch_bounds__(256, 1)
main_kernel(const float* __restrict__ W_hh, const float* __restrict__ b_hh) {
    extern __shared__ __align__(16) unsigned char smraw[];
    __half* Wsm = (__half*)(smraw + OFF_W);
    float* Sloc = (float*)(smraw + OFF_SLOC);
    float* Xs   = (float*)(smraw + OFF_XS);
    float* Ks   = (float*)(smraw + OFF_KS);
    float* fcs  = (float*)(smraw + OFF_FCS);
    float* bhs  = (float*)(smraw + OFF_BHS);

    const int tid  = threadIdx.x;
    const int lane = tid & 31;
    const int wm   = tid >> 5;
    const int bn   = blockIdx.x & 31;
    const int bm   = blockIdx.x >> 5;
    const int N0   = bn * 32;
    const int batch0 = bm * 64;
    const bool isx = (wm < 4);

    const uint32_t sbase = smem_u32(smraw);
    const uint32_t abase = sbase + OFF_A;
    const unsigned fbase = (unsigned)(bm * 32) * 32u;   // flag index base of group

    // ---- one-time: W slice -> smem fp16 ----
    for (int i4 = tid; i4 < 32 * 256; i4 += 256) {
        int r = i4 >> 8, kpos = (i4 & 255) * 4;
        float4 w = __ldg((const float4*)(W_hh + (N0 + r) * N_SZ + kpos));
        __half2* p = (__half2*)(Wsm + r * WSTR_H + kpos);
        p[0] = __floats2half2_rn(w.x, w.y);
        p[1] = __floats2half2_rn(w.z, w.w);
    }
    for (int i = tid; i < 128 * LSTR; i += 256) { Sloc[i] = 0.0f; Xs[i] = 0.0f; Ks[i] = 0.0f; }
    if (tid < 32) { fcs[tid] = g_fc[N0 + tid]; bhs[tid] = __ldg(b_hh + N0 + tid); }
    __syncthreads();

    // ---- cp.async loader mapping ----
    int gofs[4];
    uint32_t sofs[4];
    {
        const int cg = tid & 7;
#pragma unroll
        for (int i = 0; i < 4; ++i) {
            int arow = (tid >> 3) + 32 * i;
            int grow = (arow < 64) ? (batch0 + arow) : (256 + batch0 + arow - 64);
            gofs[i] = grow * N_SZ + cg * 8;
            sofs[i] = (uint32_t)(arow * ASTR_H + cg * 8) * 2;
        }
    }

    // ---- ldmatrix lane addresses ----
    const uint32_t aoff_l =
        (uint32_t)(((wm * 16 + (lane & 7) + ((lane & 8) ? 8 : 0)) * ASTR_H
                    + ((lane & 16) ? 8 : 0)) * 2);
    uint32_t woff[2];
#pragma unroll
    for (int p = 0; p < 2; ++p)
        woff[p] = sbase + OFF_W +
            (uint32_t)(((p * 16 + (lane & 7) + ((lane & 16) ? 8 : 0)) * WSTR_H
                        + ((lane & 8) ? 8 : 0)) * 2);

    for (int sig = 0; sig < 4 * T_STEPS; ++sig) {
        const int t = sig >> 2;
        const int s = sig & 3;
        const __half* Sin = g_Sb[(sig + 3) & 3];
        __half*       Sout = g_Sb[sig & 3];
        const unsigned need = (unsigned)sig;

        float acc[4][4];
#pragma unroll
        for (int i = 0; i < 4; ++i)
#pragma unroll
            for (int j = 0; j < 4; ++j) acc[i][j] = 0.0f;

        // prologue: chunks 0,1 (poll producers, then issue)
#pragma unroll
        for (int st = 0; st < 2; ++st) {
            wait_flag(&g_done[fbase + (unsigned)(2 * st) * 32u], need);
            wait_flag(&g_done[fbase + (unsigned)(2 * st + 1) * 32u], need);
            const uint32_t ab = abase + st * ABUF_B;
#pragma unroll
            for (int i = 0; i < 4; ++i)
                cp16(ab + sofs[i], Sin + gofs[i] + st * BK);
            cp_commit();
        }

        for (int c = 0; c < NCHUNK; ++c) {
            if (c == NCHUNK - 1)
                asm volatile("cp.async.wait_group 0;" ::: "memory");
            else
                asm volatile("cp.async.wait_group 1;" ::: "memory");
            __syncthreads();

            if (c + 2 < NCHUNK) {
                const int st = c + 2;
                wait_flag(&g_done[fbase + (unsigned)(2 * st) * 32u], need);
                wait_flag(&g_done[fbase + (unsigned)(2 * st + 1) * 32u], need);
                const uint32_t ab = abase + (st % 3) * ABUF_B;
#pragma unroll
                for (int i = 0; i < 4; ++i)
                    cp16(ab + sofs[i], Sin + gofs[i] + st * BK);
                cp_commit();
            }

            const uint32_t ab = abase + (c % 3) * ABUF_B;
            const uint32_t wk = (uint32_t)(c * BK * 2);
#pragma unroll
            for (int kk = 0; kk < BK; kk += 16) {
                uint32_t a0, a1, a2, a3;
                ldsm4(a0, a1, a2, a3, ab + aoff_l + kk * 2);
                uint32_t b00, b01, b10, b11;
                ldsm4(b00, b01, b10, b11, woff[0] + wk + kk * 2);
                uint32_t b20, b21, b30, b31;
                ldsm4(b20, b21, b30, b31, woff[1] + wk + kk * 2);
                mma_f16(acc[0], a0, a1, a2, a3, b00, b01);
                mma_f16(acc[1], a0, a1, a2, a3, b10, b11);
                mma_f16(acc[2], a0, a1, a2, a3, b20, b21);
                mma_f16(acc[3], a0, a1, a2, a3, b30, b31);
            }
        }

        // ---------------- fused RK4-stage epilogue (SMEM-local state) -------
        const float cmul = (s == 2) ? C_H : 0.5f * C_H;
        const int r0 = wm * 16 + (lane >> 2);
        float kv[4][4];
#pragma unroll
        for (int nt = 0; nt < 4; ++nt) {
#pragma unroll
            for (int e = 0; e < 4; ++e) {
                const int rl = r0 + 8 * (e >> 1);
                const int cl = nt * 8 + 2 * (lane & 3) + (e & 1);
                const int rx = isx ? rl : rl - 64;
                const float sx = Sloc[rx * LSTR + cl];
                const float sy = Sloc[(rx + 64) * LSTR + cl];
                const float amp = C_LAM - (sx * sx + sy * sy);
                const float rr = acc[nt][e];
                float k;
                if (isx) {
                    float F = (t == 0) ? g_F0[(batch0 + rx) * N_SZ + N0 + cl] : fcs[cl];
                    k = amp * sx - C_OMEGA * sy + C_GAIN * (rr + bhs[cl]) + F - C_GAMMA * sx;
                } else {
                    k = amp * sy + C_OMEGA * sx + C_GAIN * (rr + bhs[cl]) - C_GAMMA * sy;
                }
                kv[nt][e] = k;
            }
        }
        __syncthreads();  // all Sloc reads done before overwrites
#pragma unroll
        for (int nt = 0; nt < 4; ++nt) {
#pragma unroll
            for (int eh = 0; eh < 2; ++eh) {
                const int rl  = r0 + 8 * eh;
                const int cl0 = nt * 8 + 2 * (lane & 3);
                float sv[2];
#pragma unroll
                for (int j = 0; j < 2; ++j) {
                    const int il = rl * LSTR + cl0 + j;
                    const float k = kv[nt][eh * 2 + j];
                    const float xv = Xs[il];
                    float v;
                    if (s == 0)      { Ks[il] = k;                        v = xv + cmul * k; }
                    else if (s == 3) { float xn = xv + (C_H / 6.0f) * (Ks[il] + k);
                                       Xs[il] = xn;                       v = xn; }
                    else             { Ks[il] += 2.0f * k;                v = xv + cmul * k; }
                    Sloc[il] = v;
                    sv[j] = v;
                }
                const int grow = batch0 + rl + (isx ? 0 : 192);
                const int gi = grow * N_SZ + N0 + cl0;
                *(__half2*)(Sout + gi) = __floats2half2_rn(sv[0], sv[1]);
                if (sig == 4 * T_STEPS - 1)
                    *(float2*)(g_X + gi) = make_float2(sv[0], sv[1]);
            }
        }

        // ---- publish: all stores done -> release own flag ----
        __syncthreads();
        if (tid == 0) {
            __threadfence();
            asm volatile("st.release.gpu.u32 [%0], %1;"
                         :: "l"(&g_done[fbase + (unsigned)bn * 32u]),
                            "r"((unsigned)(sig + 1)) : "memory");
        }
    }
}

// ---------------------------------------------------------------------------
__global__ void out_kernel(const float* __restrict__ W_ho,
                           const float* __restrict__ b_ho,
                           float* __restrict__ out) {
    int b   = blockIdx.x;
    int tid = threadIdx.x;
    int o   = tid >> 2;
    int q   = tid & 3;
    const float4* xp = (const float4*)(g_X + b * N_SZ + q * 256);
    const float4* wp = (const float4*)(W_ho + o * N_SZ + q * 256);
    float s = 0.0f;
#pragma unroll 8
    for (int i = 0; i < 64; ++i) {
        float4 x = xp[i];
        float4 w = __ldg(wp + i);
        s += x.x * w.x + x.y * w.y + x.z * w.z + x.w * w.w;
    }
    s += __shfl_xor_sync(0xffffffffu, s, 1);
    s += __shfl_xor_sync(0xffffffffu, s, 2);
    if (q == 0) out[b * O_SZ + o] = s + __ldg(b_ho + o);
}

// ---------------------------------------------------------------------------
extern "C" void kernel_launch(void* const* d_in, const int* in_sizes, int n_in,
                              void* d_out, int out_size) {
    const float* batch = (const float*)d_in[0];
    const float* W_ih  = (const float*)d_in[1];
    const float* b_ih  = (const float*)d_in[2];
    const float* W_hh  = (const float*)d_in[3];
    const float* b_hh  = (const float*)d_in[4];
    const float* W_ho  = (const float*)d_in[5];
    const float* b_ho  = (const float*)d_in[6];
    float* out = (float*)d_out;

    cudaFuncSetAttribute(main_kernel,
                         cudaFuncAttributeMaxDynamicSharedMemorySize, SMEM_BYTES);

    init_kernel<<<512, 256>>>(b_ih);
    forcing_kernel<<<(B_SZ * N_SZ) / 256, 256>>>(batch, W_ih, b_ih);
    main_kernel<<<GRID_MAIN, 256, SMEM_BYTES>>>(W_hh, b_hh);
    out_kernel<<<B_SZ, 256>>>(W_ho, b_ho, out);
}

// round 8
// speedup vs baseline: 2.1208x; 2.1208x over previous
#include <cuda_runtime.h>
#include <cuda_fp16.h>
#include <math.h>
#include <stdint.h>

#define T_STEPS 256
#define B_SZ    256
#define I_SZ    128
#define N_SZ    1024
#define O_SZ    64
#define M_ROWS  512

#define GRID_MAIN 128
#define BK 64              // k per chunk (halves)
#define NCHUNK (N_SZ / BK) // 16
#define LSTR 33

#define WSTR_H 1032        // W smem row stride (halves)
#define ASTR_H 72          // A smem row stride (halves)
#define ABUF_B 18432       // one A buffer: 128 * 72 * 2

// ---- shared memory byte offsets ----
#define OFF_W     0                        // 32*1032*2 = 66048
#define OFF_A     66048                    // 3 x 18432 = 55296
#define OFF_SLOC  121344                   // 128*33 floats
#define OFF_XS    138240
#define OFF_KS    155136
#define OFF_FCS   172032
#define OFF_BHS   172160
#define SMEM_BYTES 172288

__device__ __half g_Sb[4][M_ROWS * N_SZ];  // rotating state buffers (fp16)
__device__ float  g_X [M_ROWS * N_SZ];
__device__ float  g_F0[B_SZ * N_SZ];
__device__ float  g_fc[N_SZ];
__device__ unsigned g_done[128 * 32];      // per-CTA stage counter, 128B padded

__constant__ float C_H     = 0.05f;
__constant__ float C_OMEGA = 6.283185307179586f;
__constant__ float C_GAMMA = 0.1f;
__constant__ float C_LAM   = 1.0f;
__constant__ float C_GAIN  = 0.03125f;

// ---------------------------------------------------------------------------
__global__ void init_kernel(const float* __restrict__ b_ih) {
    int idx = blockIdx.x * blockDim.x + threadIdx.x;
    int stride = gridDim.x * blockDim.x;
    for (int i = idx; i < M_ROWS * N_SZ; i += stride) g_Sb[3][i] = __float2half(0.0f);
    for (int i = idx; i < 128 * 32; i += stride) g_done[i] = 0u;
    if (idx < N_SZ) g_fc[idx] = tanhf(b_ih[idx]);
}

__global__ void forcing_kernel(const float* __restrict__ batch,
                               const float* __restrict__ W_ih,
                               const float* __restrict__ b_ih) {
    int idx = blockIdx.x * blockDim.x + threadIdx.x;
    int b = idx >> 10;
    int n = idx & (N_SZ - 1);
    const float4* xp = (const float4*)(batch + b * I_SZ);
    const float4* wp = (const float4*)(W_ih + n * I_SZ);
    float s = 0.0f;
#pragma unroll 8
    for (int i = 0; i < I_SZ / 4; ++i) {
        float4 x = __ldg(xp + i);
        float4 w = __ldg(wp + i);
        s += x.x * w.x + x.y * w.y + x.z * w.z + x.w * w.w;
    }
    g_F0[idx] = tanhf(s + __ldg(b_ih + n));
}

// ---------------------------------------------------------------------------
__device__ __forceinline__ void wait_flag(const unsigned* p, unsigned need) {
    unsigned v;
    do {
        asm volatile("ld.acquire.gpu.u32 %0, [%1];" : "=r"(v) : "l"(p) : "memory");
    } while (v < need);
}

// ---------------------------------------------------------------------------
__device__ __forceinline__ void mma_f16(float* d, uint32_t a0, uint32_t a1,
                                        uint32_t a2, uint32_t a3,
                                        uint32_t b0, uint32_t b1) {
    asm volatile(
        "mma.sync.aligned.m16n8k16.row.col.f32.f16.f16.f32 "
        "{%0,%1,%2,%3},{%4,%5,%6,%7},{%8,%9},{%0,%1,%2,%3};"
        : "+f"(d[0]), "+f"(d[1]), "+f"(d[2]), "+f"(d[3])
        : "r"(a0), "r"(a1), "r"(a2), "r"(a3), "r"(b0), "r"(b1));
}

__device__ __forceinline__ void ldsm4(uint32_t& r0, uint32_t& r1, uint32_t& r2,
                                      uint32_t& r3, uint32_t addr) {
    asm volatile("ldmatrix.sync.aligned.m8n8.x4.shared.b16 {%0,%1,%2,%3}, [%4];"
                 : "=r"(r0), "=r"(r1), "=r"(r2), "=r"(r3) : "r"(addr));
}

__device__ __forceinline__ void cp16(uint32_t s, const void* g) {
    asm volatile("cp.async.cg.shared.global [%0], [%1], 16;"
                 :: "r"(s), "l"(g) : "memory");
}
__device__ __forceinline__ void cp_commit() {
    asm volatile("cp.async.commit_group;" ::: "memory");
}

__device__ __forceinline__ uint32_t smem_u32(const void* p) {
    uint32_t a;
    asm("{ .reg .u64 t; cvta.to.shared.u64 t, %1; cvt.u32.u64 %0, t; }" : "=r"(a) : "l"(p));
    return a;
}

// ---------------------------------------------------------------------------
// main persistent kernel — flag-synced pipeline, single-warp polling.
// Grid 128 = 4 independent 32-CTA groups. Output of stage sig -> g_Sb[sig&3].
// ---------------------------------------------------------------------------
__global__ void __launch_bounds__(256, 1)
main_kernel(const float* __restrict__ W_hh, const float* __restrict__ b_hh) {
    extern __shared__ __align__(16) unsigned char smraw[];
    __half* Wsm = (__half*)(smraw + OFF_W);
    float* Sloc = (float*)(smraw + OFF_SLOC);
    float* Xs   = (float*)(smraw + OFF_XS);
    float* Ks   = (float*)(smraw + OFF_KS);
    float* fcs  = (float*)(smraw + OFF_FCS);
    float* bhs  = (float*)(smraw + OFF_BHS);

    const int tid  = threadIdx.x;
    const int lane = tid & 31;
    const int wm   = tid >> 5;
    const int bn   = blockIdx.x & 31;
    const int bm   = blockIdx.x >> 5;
    const int N0   = bn * 32;
    const int batch0 = bm * 64;
    const bool isx = (wm < 4);

    const uint32_t sbase = smem_u32(smraw);
    const uint32_t abase = sbase + OFF_A;
    const unsigned fbase = (unsigned)(bm * 32) * 32u;   // flag index base of group

    // ---- one-time: W slice -> smem fp16 ----
    for (int i4 = tid; i4 < 32 * 256; i4 += 256) {
        int r = i4 >> 8, kpos = (i4 & 255) * 4;
        float4 w = __ldg((const float4*)(W_hh + (N0 + r) * N_SZ + kpos));
        __half2* p = (__half2*)(Wsm + r * WSTR_H + kpos);
        p[0] = __floats2half2_rn(w.x, w.y);
        p[1] = __floats2half2_rn(w.z, w.w);
    }
    for (int i = tid; i < 128 * LSTR; i += 256) { Sloc[i] = 0.0f; Xs[i] = 0.0f; Ks[i] = 0.0f; }
    if (tid < 32) { fcs[tid] = g_fc[N0 + tid]; bhs[tid] = __ldg(b_hh + N0 + tid); }
    __syncthreads();

    // ---- cp.async loader mapping ----
    int gofs[4];
    uint32_t sofs[4];
    {
        const int cg = tid & 7;
#pragma unroll
        for (int i = 0; i < 4; ++i) {
            int arow = (tid >> 3) + 32 * i;
            int grow = (arow < 64) ? (batch0 + arow) : (256 + batch0 + arow - 64);
            gofs[i] = grow * N_SZ + cg * 8;
            sofs[i] = (uint32_t)(arow * ASTR_H + cg * 8) * 2;
        }
    }

    // ---- ldmatrix lane addresses ----
    const uint32_t aoff_l =
        (uint32_t)(((wm * 16 + (lane & 7) + ((lane & 8) ? 8 : 0)) * ASTR_H
                    + ((lane & 16) ? 8 : 0)) * 2);
    uint32_t woff[2];
#pragma unroll
    for (int p = 0; p < 2; ++p)
        woff[p] = sbase + OFF_W +
            (uint32_t)(((p * 16 + (lane & 7) + ((lane & 16) ? 8 : 0)) * WSTR_H
                        + ((lane & 8) ? 8 : 0)) * 2);

    for (int sig = 0; sig < 4 * T_STEPS; ++sig) {
        const int t = sig >> 2;
        const int s = sig & 3;
        const __half* Sin = g_Sb[(sig + 3) & 3];
        __half*       Sout = g_Sb[sig & 3];
        const unsigned need = (unsigned)sig;

        float acc[4][4];
#pragma unroll
        for (int i = 0; i < 4; ++i)
#pragma unroll
            for (int j = 0; j < 4; ++j) acc[i][j] = 0.0f;

        // ---- wait phase A: producers of chunks 0,1 (group CTAs 0..3) ----
        if (wm == 0 && lane < 4)
            wait_flag(&g_done[fbase + (unsigned)lane * 32u], need);
        __syncthreads();

        // prologue: chunks 0,1
#pragma unroll
        for (int st = 0; st < 2; ++st) {
            const uint32_t ab = abase + st * ABUF_B;
#pragma unroll
            for (int i = 0; i < 4; ++i)
                cp16(ab + sofs[i], Sin + gofs[i] + st * BK);
            cp_commit();
        }

        // ---- wait phase B: remaining producers (group CTAs 4..31) ----
        if (wm == 0 && lane >= 4)
            wait_flag(&g_done[fbase + (unsigned)lane * 32u], need);
        __syncthreads();

        for (int c = 0; c < NCHUNK; ++c) {
            if (c == NCHUNK - 1)
                asm volatile("cp.async.wait_group 0;" ::: "memory");
            else
                asm volatile("cp.async.wait_group 1;" ::: "memory");
            __syncthreads();

            if (c + 2 < NCHUNK) {
                const int st = c + 2;
                const uint32_t ab = abase + (st % 3) * ABUF_B;
#pragma unroll
                for (int i = 0; i < 4; ++i)
                    cp16(ab + sofs[i], Sin + gofs[i] + st * BK);
                cp_commit();
            }

            const uint32_t ab = abase + (c % 3) * ABUF_B;
            const uint32_t wk = (uint32_t)(c * BK * 2);
#pragma unroll
            for (int kk = 0; kk < BK; kk += 16) {
                uint32_t a0, a1, a2, a3;
                ldsm4(a0, a1, a2, a3, ab + aoff_l + kk * 2);
                uint32_t b00, b01, b10, b11;
                ldsm4(b00, b01, b10, b11, woff[0] + wk + kk * 2);
                uint32_t b20, b21, b30, b31;
                ldsm4(b20, b21, b30, b31, woff[1] + wk + kk * 2);
                mma_f16(acc[0], a0, a1, a2, a3, b00, b01);
                mma_f16(acc[1], a0, a1, a2, a3, b10, b11);
                mma_f16(acc[2], a0, a1, a2, a3, b20, b21);
                mma_f16(acc[3], a0, a1, a2, a3, b30, b31);
            }
        }

        // ---------------- fused RK4-stage epilogue (SMEM-local state) -------
        const float cmul = (s == 2) ? C_H : 0.5f * C_H;
        const int r0 = wm * 16 + (lane >> 2);
        float kv[4][4];
#pragma unroll
        for (int nt = 0; nt < 4; ++nt) {
#pragma unroll
            for (int e = 0; e < 4; ++e) {
                const int rl = r0 + 8 * (e >> 1);
                const int cl = nt * 8 + 2 * (lane & 3) + (e & 1);
                const int rx = isx ? rl : rl - 64;
                const float sx = Sloc[rx * LSTR + cl];
                const float sy = Sloc[(rx + 64) * LSTR + cl];
                const float amp = C_LAM - (sx * sx + sy * sy);
                const float rr = acc[nt][e];
                float k;
                if (isx) {
                    float F = (t == 0) ? g_F0[(batch0 + rx) * N_SZ + N0 + cl] : fcs[cl];
                    k = amp * sx - C_OMEGA * sy + C_GAIN * (rr + bhs[cl]) + F - C_GAMMA * sx;
                } else {
                    k = amp * sy + C_OMEGA * sx + C_GAIN * (rr + bhs[cl]) - C_GAMMA * sy;
                }
                kv[nt][e] = k;
            }
        }
        __syncthreads();  // all Sloc reads done before overwrites
#pragma unroll
        for (int nt = 0; nt < 4; ++nt) {
#pragma unroll
            for (int eh = 0; eh < 2; ++eh) {
                const int rl  = r0 + 8 * eh;
                const int cl0 = nt * 8 + 2 * (lane & 3);
                float sv[2];
#pragma unroll
                for (int j = 0; j < 2; ++j) {
                    const int il = rl * LSTR + cl0 + j;
                    const float k = kv[nt][eh * 2 + j];
                    const float xv = Xs[il];
                    float v;
                    if (s == 0)      { Ks[il] = k;                        v = xv + cmul * k; }
                    else if (s == 3) { float xn = xv + (C_H / 6.0f) * (Ks[il] + k);
                                       Xs[il] = xn;                       v = xn; }
                    else             { Ks[il] += 2.0f * k;                v = xv + cmul * k; }
                    Sloc[il] = v;
                    sv[j] = v;
                }
                const int grow = batch0 + rl + (isx ? 0 : 192);
                const int gi = grow * N_SZ + N0 + cl0;
                *(__half2*)(Sout + gi) = __floats2half2_rn(sv[0], sv[1]);
                if (sig == 4 * T_STEPS - 1)
                    *(float2*)(g_X + gi) = make_float2(sv[0], sv[1]);
            }
        }

        // ---- publish: all stores done -> release own flag (tid0 only) ----
        __syncthreads();
        if (tid == 0) {
            __threadfence();
            asm volatile("st.release.gpu.u32 [%0], %1;"
                         :: "l"(&g_done[fbase + (unsigned)bn * 32u]),
                            "r"((unsigned)(sig + 1)) : "memory");
        }
    }
}

// ---------------------------------------------------------------------------
__global__ void out_kernel(const float* __restrict__ W_ho,
                           const float* __restrict__ b_ho,
                           float* __restrict__ out) {
    int b   = blockIdx.x;
    int tid = threadIdx.x;
    int o   = tid >> 2;
    int q   = tid & 3;
    const float4* xp = (const float4*)(g_X + b * N_SZ + q * 256);
    const float4* wp = (const float4*)(W_ho + o * N_SZ + q * 256);
    float s = 0.0f;
#pragma unroll 8
    for (int i = 0; i < 64; ++i) {
        float4 x = xp[i];
        float4 w = __ldg(wp + i);
        s += x.x * w.x + x.y * w.y + x.z * w.z + x.w * w.w;
    }
    s += __shfl_xor_sync(0xffffffffu, s, 1);
    s += __shfl_xor_sync(0xffffffffu, s, 2);
    if (q == 0) out[b * O_SZ + o] = s + __ldg(b_ho + o);
}

// ---------------------------------------------------------------------------
extern "C" void kernel_launch(void* const* d_in, const int* in_sizes, int n_in,
                              void* d_out, int out_size) {
    const float* batch = (const float*)d_in[0];
    const float* W_ih  = (const float*)d_in[1];
    const float* b_ih  = (const float*)d_in[2];
    const float* W_hh  = (const float*)d_in[3];
    const float* b_hh  = (const float*)d_in[4];
    const float* W_ho  = (const float*)d_in[5];
    const float* b_ho  = (const float*)d_in[6];
    float* out = (float*)d_out;

    cudaFuncSetAttribute(main_kernel,
                         cudaFuncAttributeMaxDynamicSharedMemorySize, SMEM_BYTES);

    init_kernel<<<512, 256>>>(b_ih);
    forcing_kernel<<<(B_SZ * N_SZ) / 256, 256>>>(batch, W_ih, b_ih);
    main_kernel<<<GRID_MAIN, 256, SMEM_BYTES>>>(W_hh, b_hh);
    out_kernel<<<B_SZ, 256>>>(W_ho, b_ho, out);
}